// round 2
// baseline (speedup 1.0000x reference)
#include <cuda_runtime.h>
#include <cuda_bf16.h>
#include <math.h>

#define Tn 2048
#define Dn 1024
#define Hn 4096
#define Ln 8
#define Vn 50257
#define EPSn 1e-5f

// ---------------- scratch (no allocations allowed) ----------------
__device__ float g_x [Tn*Dn];
__device__ float g_xn[Tn*Dn];
__device__ float g_xk[Tn*Dn];
__device__ float g_xv[Tn*Dn];
__device__ float g_xr[Tn*Dn];
__device__ float g_k [Tn*Dn];
__device__ float g_v [Tn*Dn];
__device__ float g_r [Tn*Dn];
__device__ float g_ry[Tn*Dn];
__device__ float g_rr[Tn*Dn];
__device__ float g_kk[Tn*Hn];

// ---------------- LayerNorm (optionally with embedding gather) ----------------
// one block per row (t), 256 threads, D=1024 -> one float4 per thread
__global__ void __launch_bounds__(256)
ln_kernel(const float* __restrict__ x, const int* __restrict__ tokens,
          const float* __restrict__ w, const float* __restrict__ b,
          float* __restrict__ y)
{
    __shared__ float sh0[8], sh1[8];
    int t = blockIdx.x;
    const float* row;
    if (tokens) row = x + (size_t)tokens[t] * Dn;
    else        row = x + (size_t)t * Dn;

    float4 vv = reinterpret_cast<const float4*>(row)[threadIdx.x];
    float s  = vv.x + vv.y + vv.z + vv.w;
    float s2 = vv.x*vv.x + vv.y*vv.y + vv.z*vv.z + vv.w*vv.w;
    #pragma unroll
    for (int o = 16; o > 0; o >>= 1) {
        s  += __shfl_down_sync(0xffffffffu, s,  o);
        s2 += __shfl_down_sync(0xffffffffu, s2, o);
    }
    int wid = threadIdx.x >> 5, lid = threadIdx.x & 31;
    if (lid == 0) { sh0[wid] = s; sh1[wid] = s2; }
    __syncthreads();
    if (threadIdx.x < 32) {
        s  = (lid < 8) ? sh0[lid] : 0.f;
        s2 = (lid < 8) ? sh1[lid] : 0.f;
        #pragma unroll
        for (int o = 4; o > 0; o >>= 1) {
            s  += __shfl_down_sync(0xffffffffu, s,  o);
            s2 += __shfl_down_sync(0xffffffffu, s2, o);
        }
        if (lid == 0) { sh0[0] = s; sh1[0] = s2; }
    }
    __syncthreads();
    float mu  = sh0[0] * (1.f / Dn);
    float var = sh1[0] * (1.f / Dn) - mu * mu;
    float rstd = rsqrtf(var + EPSn);

    float4 wv = reinterpret_cast<const float4*>(w)[threadIdx.x];
    float4 bv = reinterpret_cast<const float4*>(b)[threadIdx.x];
    float4 o4;
    o4.x = (vv.x - mu) * rstd * wv.x + bv.x;
    o4.y = (vv.y - mu) * rstd * wv.y + bv.y;
    o4.z = (vv.z - mu) * rstd * wv.z + bv.z;
    o4.w = (vv.w - mu) * rstd * wv.w + bv.w;
    reinterpret_cast<float4*>(y + (size_t)t * Dn)[threadIdx.x] = o4;
}

// ---------------- time-shift mixes ----------------
__global__ void __launch_bounds__(256)
mix3_kernel(const float* __restrict__ x,
            const float* __restrict__ mk, const float* __restrict__ mv,
            const float* __restrict__ mr,
            float* __restrict__ xk, float* __restrict__ xv, float* __restrict__ xr)
{
    int i = blockIdx.x * 256 + threadIdx.x;
    if (i >= Tn * Dn) return;
    int d = i & (Dn - 1);
    float c = x[i];
    float p = (i >= Dn) ? x[i - Dn] : 0.f;
    float a;
    a = mk[d]; xk[i] = c * a + p * (1.f - a);
    a = mv[d]; xv[i] = c * a + p * (1.f - a);
    a = mr[d]; xr[i] = c * a + p * (1.f - a);
}

__global__ void __launch_bounds__(256)
mix2_kernel(const float* __restrict__ x,
            const float* __restrict__ mk, const float* __restrict__ mr,
            float* __restrict__ xk, float* __restrict__ xr)
{
    int i = blockIdx.x * 256 + threadIdx.x;
    if (i >= Tn * Dn) return;
    int d = i & (Dn - 1);
    float c = x[i];
    float p = (i >= Dn) ? x[i - Dn] : 0.f;
    float a;
    a = mk[d]; xk[i] = c * a + p * (1.f - a);
    a = mr[d]; xr[i] = c * a + p * (1.f - a);
}

// ---------------- WKV scan (T-sequential, D-parallel) ----------------
__global__ void __launch_bounds__(256)
wkv_kernel(const float* __restrict__ td, const float* __restrict__ tf,
           const float* __restrict__ k, const float* __restrict__ v,
           const float* __restrict__ r, float* __restrict__ ry)
{
    int d = blockIdx.x * 256 + threadIdx.x;
    if (d >= Dn) return;
    float w = -expf(td[d]);
    float u = tf[d];
    float aa = 0.f, bb = 0.f, pp = -1e30f;
    float kt = k[d], vt = v[d];
    for (int t = 0; t < Tn; t++) {
        float kn = 0.f, vn = 0.f;
        if (t + 1 < Tn) { kn = k[(t + 1) * Dn + d]; vn = v[(t + 1) * Dn + d]; }
        float ww = u + kt;
        float qq = fmaxf(pp, ww);
        float e1 = __expf(pp - qq), e2 = __expf(ww - qq);
        float out = fmaf(e1, aa, e2 * vt) / fmaf(e1, bb, e2);
        float ww2 = pp + w;
        float qq2 = fmaxf(ww2, kt);
        e1 = __expf(ww2 - qq2); e2 = __expf(kt - qq2);
        aa = fmaf(e1, aa, e2 * vt);
        bb = fmaf(e1, bb, e2);
        pp = qq2;
        ry[t * Dn + d] = r[t * Dn + d] * out;
        kt = kn; vt = vn;
    }
}

// ---------------- SGEMM with fused epilogues ----------------
// C[M,N] = epilogue(A[M,K] @ B[K,N])
// EPI: 0 = store, 1 = acc + X1, 2 = relu(acc)^2, 3 = sigmoid(acc), 4 = X1 + X2*acc
template<int EPI>
__global__ void __launch_bounds__(256)
sgemm_kernel(const float* __restrict__ A, const float* __restrict__ B,
             float* __restrict__ C, int M, int N, int K,
             const float* __restrict__ X1, const float* __restrict__ X2)
{
    __shared__ float As[8][128];
    __shared__ float Bs[8][132];

    const int tid = threadIdx.x;
    const int tx = tid & 15;          // 16 cols of threads
    const int ty = tid >> 4;          // 16 rows of threads
    const int bm = blockIdx.y * 128;
    const int bn = blockIdx.x * 128;

    const int arow = tid >> 1;            // 0..127
    const int acol = (tid & 1) << 2;      // 0 or 4
    const int brow = tid >> 5;            // 0..7
    const int bcol = (tid & 31) << 2;     // 0..124

    float acc[8][8];
    #pragma unroll
    for (int i = 0; i < 8; i++)
        #pragma unroll
        for (int j = 0; j < 8; j++) acc[i][j] = 0.f;

    const float* Aptr = A + (size_t)(bm + arow) * K + acol;
    const bool nvec = ((N & 3) == 0);

    for (int k0 = 0; k0 < K; k0 += 8) {
        // A tile (always in-bounds: M%128==0, K%8==0), store transposed
        float4 a4 = *reinterpret_cast<const float4*>(Aptr + k0);
        As[acol + 0][arow] = a4.x;
        As[acol + 1][arow] = a4.y;
        As[acol + 2][arow] = a4.z;
        As[acol + 3][arow] = a4.w;

        // B tile (guard columns; scalar path when N not 4-aligned)
        const float* p = B + (size_t)(k0 + brow) * N;
        int gc = bn + bcol;
        float4 b4;
        if (nvec && gc + 3 < N) {
            b4 = *reinterpret_cast<const float4*>(p + gc);
        } else {
            b4.x = (gc + 0 < N) ? p[gc + 0] : 0.f;
            b4.y = (gc + 1 < N) ? p[gc + 1] : 0.f;
            b4.z = (gc + 2 < N) ? p[gc + 2] : 0.f;
            b4.w = (gc + 3 < N) ? p[gc + 3] : 0.f;
        }
        *reinterpret_cast<float4*>(&Bs[brow][bcol]) = b4;

        __syncthreads();

        #pragma unroll
        for (int kk = 0; kk < 8; kk++) {
            float ra[8], rb[8];
            *reinterpret_cast<float4*>(ra)     = *reinterpret_cast<const float4*>(&As[kk][ty * 8]);
            *reinterpret_cast<float4*>(ra + 4) = *reinterpret_cast<const float4*>(&As[kk][ty * 8 + 4]);
            *reinterpret_cast<float4*>(rb)     = *reinterpret_cast<const float4*>(&Bs[kk][tx * 8]);
            *reinterpret_cast<float4*>(rb + 4) = *reinterpret_cast<const float4*>(&Bs[kk][tx * 8 + 4]);
            #pragma unroll
            for (int i = 0; i < 8; i++)
                #pragma unroll
                for (int j = 0; j < 8; j++)
                    acc[i][j] = fmaf(ra[i], rb[j], acc[i][j]);
        }
        __syncthreads();
    }

    #pragma unroll
    for (int i = 0; i < 8; i++) {
        int row = bm + ty * 8 + i;
        float* crow = C + (size_t)row * N;
        #pragma unroll
        for (int j = 0; j < 8; j++) {
            int col = bn + tx * 8 + j;
            if (col < N) {
                float a = acc[i][j];
                if (EPI == 0) {
                    crow[col] = a;
                } else if (EPI == 1) {
                    crow[col] = a + X1[(size_t)row * N + col];
                } else if (EPI == 2) {
                    float tpos = fmaxf(a, 0.f);
                    crow[col] = tpos * tpos;
                } else if (EPI == 3) {
                    crow[col] = 1.f / (1.f + expf(-a));
                } else {
                    crow[col] = X1[(size_t)row * N + col]
                              + X2[(size_t)row * N + col] * a;
                }
            }
        }
    }
}

// ---------------- host orchestration ----------------
extern "C" void kernel_launch(void* const* d_in, const int* in_sizes, int n_in,
                              void* d_out, int out_size)
{
    const int*   tokens   = (const int*)  d_in[0];
    const float* emb      = (const float*)d_in[1];
    const float* tm_decay = (const float*)d_in[2];
    const float* tm_first = (const float*)d_in[3];
    const float* tm_mix_k = (const float*)d_in[4];
    const float* tm_mix_v = (const float*)d_in[5];
    const float* tm_mix_r = (const float*)d_in[6];
    const float* tm_Wk    = (const float*)d_in[7];
    const float* tm_Wv    = (const float*)d_in[8];
    const float* tm_Wr    = (const float*)d_in[9];
    const float* tm_Wo    = (const float*)d_in[10];
    const float* cm_mix_k = (const float*)d_in[11];
    const float* cm_mix_r = (const float*)d_in[12];
    const float* cm_Wk    = (const float*)d_in[13];
    const float* cm_Wv    = (const float*)d_in[14];
    const float* cm_Wr    = (const float*)d_in[15];
    const float* ln0_w    = (const float*)d_in[16];
    const float* ln0_b    = (const float*)d_in[17];
    const float* ln1_w    = (const float*)d_in[18];
    const float* ln1_b    = (const float*)d_in[19];
    const float* ln2_w    = (const float*)d_in[20];
    const float* ln2_b    = (const float*)d_in[21];
    const float* lnout_w  = (const float*)d_in[22];
    const float* lnout_b  = (const float*)d_in[23];
    const float* head_W   = (const float*)d_in[24];
    float* out = (float*)d_out;

    float *x_, *xn_, *xk_, *xv_, *xr_, *k_, *v_, *r_, *ry_, *rr_, *kk_;
    cudaGetSymbolAddress((void**)&x_,  g_x);
    cudaGetSymbolAddress((void**)&xn_, g_xn);
    cudaGetSymbolAddress((void**)&xk_, g_xk);
    cudaGetSymbolAddress((void**)&xv_, g_xv);
    cudaGetSymbolAddress((void**)&xr_, g_xr);
    cudaGetSymbolAddress((void**)&k_,  g_k);
    cudaGetSymbolAddress((void**)&v_,  g_v);
    cudaGetSymbolAddress((void**)&r_,  g_r);
    cudaGetSymbolAddress((void**)&ry_, g_ry);
    cudaGetSymbolAddress((void**)&rr_, g_rr);
    cudaGetSymbolAddress((void**)&kk_, g_kk);

    const int ew = (Tn * Dn + 255) / 256;   // elementwise grid
    dim3 gDD(Dn / 128, Tn / 128);           // [T,D] x [D,D]
    dim3 gDH(Hn / 128, Tn / 128);           // [T,D] x [D,H]
    dim3 gHV((Vn + 127) / 128, Tn / 128);   // head

    // embedding gather + ln0
    ln_kernel<<<Tn, 256>>>(emb, tokens, ln0_w, ln0_b, x_);

    for (int l = 0; l < Ln; l++) {
        const float* Wk  = tm_Wk + (size_t)l * Dn * Dn;
        const float* Wv  = tm_Wv + (size_t)l * Dn * Dn;
        const float* Wr  = tm_Wr + (size_t)l * Dn * Dn;
        const float* Wo  = tm_Wo + (size_t)l * Dn * Dn;
        const float* CWk = cm_Wk + (size_t)l * Dn * Hn;
        const float* CWv = cm_Wv + (size_t)l * Hn * Dn;
        const float* CWr = cm_Wr + (size_t)l * Dn * Dn;

        // ln1 (in-place; ln output becomes the residual stream)
        ln_kernel<<<Tn, 256>>>(x_, nullptr, ln1_w + l * Dn, ln1_b + l * Dn, x_);

        // time-mix inputs
        mix3_kernel<<<ew, 256>>>(x_, tm_mix_k + l * Dn, tm_mix_v + l * Dn,
                                 tm_mix_r + l * Dn, xk_, xv_, xr_);

        sgemm_kernel<0><<<gDD, 256>>>(xk_, Wk, k_, Tn, Dn, Dn, nullptr, nullptr);
        sgemm_kernel<0><<<gDD, 256>>>(xv_, Wv, v_, Tn, Dn, Dn, nullptr, nullptr);
        sgemm_kernel<3><<<gDD, 256>>>(xr_, Wr, r_, Tn, Dn, Dn, nullptr, nullptr);

        // WKV scan, writes r*y directly
        wkv_kernel<<<Dn / 256, 256>>>(tm_decay + l * Dn, tm_first + l * Dn,
                                      k_, v_, r_, ry_);

        // x = x + (r*y) @ Wo
        sgemm_kernel<1><<<gDD, 256>>>(ry_, Wo, x_, Tn, Dn, Dn, x_, nullptr);

        // channel mix
        ln_kernel<<<Tn, 256>>>(x_, nullptr, ln2_w + l * Dn, ln2_b + l * Dn, xn_);
        mix2_kernel<<<ew, 256>>>(xn_, cm_mix_k + l * Dn, cm_mix_r + l * Dn, xk_, xr_);

        sgemm_kernel<2><<<gDH, 256>>>(xk_, CWk, kk_, Tn, Hn, Dn, nullptr, nullptr); // relu^2
        sgemm_kernel<3><<<gDD, 256>>>(xr_, CWr, rr_, Tn, Dn, Dn, nullptr, nullptr); // sigmoid
        // x = x + rr * (kk @ CWv)
        sgemm_kernel<4><<<gDD, 256>>>(kk_, CWv, x_, Tn, Dn, Hn, x_, rr_);
    }

    // final LN + head
    ln_kernel<<<Tn, 256>>>(x_, nullptr, lnout_w, lnout_b, xn_);
    sgemm_kernel<0><<<gHV, 256>>>(xn_, head_W, out, Tn, Vn, Dn, nullptr, nullptr);
}

// round 3
// speedup vs baseline: 1.1825x; 1.1825x over previous
#include <cuda_runtime.h>
#include <cuda_bf16.h>
#include <math.h>

#define Tn 2048
#define Dn 1024
#define Hn 4096
#define Ln 8
#define Vn 50257
#define VP 50304              // Vn padded up to multiple of 128
#define EPSn 1e-5f

// ---------------- scratch (no allocations allowed) ----------------
__device__ float g_x [Tn*Dn];
__device__ float g_xn[Tn*Dn];
__device__ float g_xk[Tn*Dn];
__device__ float g_xv[Tn*Dn];
__device__ float g_xr[Tn*Dn];
__device__ float g_k [Tn*Dn];
__device__ float g_v [Tn*Dn];
__device__ float g_r [Tn*Dn];
__device__ float g_ry[Tn*Dn];
__device__ float g_rr[Tn*Dn];
__device__ float g_kk[Tn*Hn];
__device__ float g_headW[(size_t)Dn * VP];   // padded head weight

// ---------------- packed f32x2 helpers (Blackwell FFMA2) ----------------
__device__ __forceinline__ unsigned long long pack2(float x, float y) {
    unsigned long long r;
    asm("mov.b64 %0, {%1, %2};" : "=l"(r) : "f"(x), "f"(y));
    return r;
}
__device__ __forceinline__ void fma2(unsigned long long& d,
                                     unsigned long long a, unsigned long long b) {
    asm("fma.rn.f32x2 %0, %1, %2, %0;" : "+l"(d) : "l"(a), "l"(b));
}
__device__ __forceinline__ void unpack2(unsigned long long v, float& lo, float& hi) {
    asm("mov.b64 {%0, %1}, %2;" : "=f"(lo), "=f"(hi) : "l"(v));
}

// ---------------- LayerNorm (optionally with embedding gather) ----------------
__global__ void __launch_bounds__(256)
ln_kernel(const float* __restrict__ x, const int* __restrict__ tokens,
          const float* __restrict__ w, const float* __restrict__ b,
          float* __restrict__ y)
{
    __shared__ float sh0[8], sh1[8];
    int t = blockIdx.x;
    const float* row;
    if (tokens) row = x + (size_t)tokens[t] * Dn;
    else        row = x + (size_t)t * Dn;

    float4 vv = reinterpret_cast<const float4*>(row)[threadIdx.x];
    float s  = vv.x + vv.y + vv.z + vv.w;
    float s2 = vv.x*vv.x + vv.y*vv.y + vv.z*vv.z + vv.w*vv.w;
    #pragma unroll
    for (int o = 16; o > 0; o >>= 1) {
        s  += __shfl_down_sync(0xffffffffu, s,  o);
        s2 += __shfl_down_sync(0xffffffffu, s2, o);
    }
    int wid = threadIdx.x >> 5, lid = threadIdx.x & 31;
    if (lid == 0) { sh0[wid] = s; sh1[wid] = s2; }
    __syncthreads();
    if (threadIdx.x < 32) {
        s  = (lid < 8) ? sh0[lid] : 0.f;
        s2 = (lid < 8) ? sh1[lid] : 0.f;
        #pragma unroll
        for (int o = 4; o > 0; o >>= 1) {
            s  += __shfl_down_sync(0xffffffffu, s,  o);
            s2 += __shfl_down_sync(0xffffffffu, s2, o);
        }
        if (lid == 0) { sh0[0] = s; sh1[0] = s2; }
    }
    __syncthreads();
    float mu  = sh0[0] * (1.f / Dn);
    float var = sh1[0] * (1.f / Dn) - mu * mu;
    float rstd = rsqrtf(var + EPSn);

    float4 wv = reinterpret_cast<const float4*>(w)[threadIdx.x];
    float4 bv = reinterpret_cast<const float4*>(b)[threadIdx.x];
    float4 o4;
    o4.x = (vv.x - mu) * rstd * wv.x + bv.x;
    o4.y = (vv.y - mu) * rstd * wv.y + bv.y;
    o4.z = (vv.z - mu) * rstd * wv.z + bv.z;
    o4.w = (vv.w - mu) * rstd * wv.w + bv.w;
    reinterpret_cast<float4*>(y + (size_t)t * Dn)[threadIdx.x] = o4;
}

// ---------------- time-shift mixes ----------------
__global__ void __launch_bounds__(256)
mix3_kernel(const float* __restrict__ x,
            const float* __restrict__ mk, const float* __restrict__ mv,
            const float* __restrict__ mr,
            float* __restrict__ xk, float* __restrict__ xv, float* __restrict__ xr)
{
    int i = blockIdx.x * 256 + threadIdx.x;
    if (i >= Tn * Dn) return;
    int d = i & (Dn - 1);
    float c = x[i];
    float p = (i >= Dn) ? x[i - Dn] : 0.f;
    float a;
    a = mk[d]; xk[i] = c * a + p * (1.f - a);
    a = mv[d]; xv[i] = c * a + p * (1.f - a);
    a = mr[d]; xr[i] = c * a + p * (1.f - a);
}

__global__ void __launch_bounds__(256)
mix2_kernel(const float* __restrict__ x,
            const float* __restrict__ mk, const float* __restrict__ mr,
            float* __restrict__ xk, float* __restrict__ xr)
{
    int i = blockIdx.x * 256 + threadIdx.x;
    if (i >= Tn * Dn) return;
    int d = i & (Dn - 1);
    float c = x[i];
    float p = (i >= Dn) ? x[i - Dn] : 0.f;
    float a;
    a = mk[d]; xk[i] = c * a + p * (1.f - a);
    a = mr[d]; xr[i] = c * a + p * (1.f - a);
}

// ---------------- WKV scan (T-sequential, D-parallel) ----------------
__global__ void __launch_bounds__(256)
wkv_kernel(const float* __restrict__ td, const float* __restrict__ tf,
           const float* __restrict__ k, const float* __restrict__ v,
           const float* __restrict__ r, float* __restrict__ ry)
{
    int d = blockIdx.x * 256 + threadIdx.x;
    if (d >= Dn) return;
    float w = -expf(td[d]);
    float u = tf[d];
    float aa = 0.f, bb = 0.f, pp = -1e30f;
    float kt = k[d], vt = v[d];
    for (int t = 0; t < Tn; t++) {
        float kn = 0.f, vn = 0.f;
        if (t + 1 < Tn) { kn = k[(t + 1) * Dn + d]; vn = v[(t + 1) * Dn + d]; }
        float ww = u + kt;
        float qq = fmaxf(pp, ww);
        float e1 = __expf(pp - qq), e2 = __expf(ww - qq);
        float out = fmaf(e1, aa, e2 * vt) / fmaf(e1, bb, e2);
        float ww2 = pp + w;
        float qq2 = fmaxf(ww2, kt);
        e1 = __expf(ww2 - qq2); e2 = __expf(kt - qq2);
        aa = fmaf(e1, aa, e2 * vt);
        bb = fmaf(e1, bb, e2);
        pp = qq2;
        ry[t * Dn + d] = r[t * Dn + d] * out;
        kt = kn; vt = vn;
    }
}

// ---------------- head weight pad-copy ([D,Vn] -> [D,VP], 16B aligned rows) ----
__global__ void __launch_bounds__(256)
padcopy_kernel(const float* __restrict__ src, float* __restrict__ dst)
{
    int r = blockIdx.y;
    for (int c = blockIdx.x * 256 + threadIdx.x; c < VP; c += gridDim.x * 256) {
        float v = (c < Vn) ? src[(size_t)r * Vn + c] : 0.f;
        dst[(size_t)r * VP + c] = v;
    }
}

// ---------------- FFMA2 SGEMM, double-buffered, fused epilogues ----------------
// C[M,N] = epilogue(A[M,K] @ B[K,N]); B has row stride ldb (>=N, mult of 4)
// EPI: 0 store, 1 acc+X1, 2 relu(acc)^2, 3 sigmoid(acc), 4 X1 + X2*acc
// CGUARD: guard C column < N (head GEMM)
template<int EPI, bool CGUARD>
__global__ void __launch_bounds__(256, 1)
sgemm2_kernel(const float* __restrict__ A, const float* __restrict__ B,
              float* __restrict__ C, int M, int N, int K, int ldb,
              const float* __restrict__ X1, const float* __restrict__ X2)
{
    // A duplicated-pair tile: AsD[stage][k][row] holds {a,a} packed (8B each)
    __shared__ unsigned long long AsD[2][16][128];   // 32 KB
    __shared__ float Bs[2][16][128];                 // 16 KB

    const int tid = threadIdx.x;
    const int tx = tid & 15;           // 16 cols of threads (8 C-cols each)
    const int ty = tid >> 4;           // 16 rows of threads (8 C-rows each)
    const int bm = blockIdx.y * 128;
    const int bn = blockIdx.x * 128;

    // A tile loaders: 128 rows x 16 cols
    const int arow = tid >> 1;
    const int ac0  = (tid & 1) * 8;
    // B tile loaders: 16 rows x 128 cols
    const int brow = tid >> 4;
    const int bc0  = (tid & 15) * 8;

    const float* Ag = A + (size_t)(bm + arow) * K + ac0;
    const float* Bg = B + (size_t)brow * ldb + bn + bc0;

    unsigned long long acc2[8][4];
    #pragma unroll
    for (int i = 0; i < 8; i++)
        #pragma unroll
        for (int j = 0; j < 4; j++) acc2[i][j] = 0ull;

    float4 ra0, ra1, rb0, rb1;

    // ---- preload tile 0 ----
    ra0 = *reinterpret_cast<const float4*>(Ag);
    ra1 = *reinterpret_cast<const float4*>(Ag + 4);
    rb0 = *reinterpret_cast<const float4*>(Bg);
    rb1 = *reinterpret_cast<const float4*>(Bg + 4);
    {
        AsD[0][ac0 + 0][arow] = pack2(ra0.x, ra0.x);
        AsD[0][ac0 + 1][arow] = pack2(ra0.y, ra0.y);
        AsD[0][ac0 + 2][arow] = pack2(ra0.z, ra0.z);
        AsD[0][ac0 + 3][arow] = pack2(ra0.w, ra0.w);
        AsD[0][ac0 + 4][arow] = pack2(ra1.x, ra1.x);
        AsD[0][ac0 + 5][arow] = pack2(ra1.y, ra1.y);
        AsD[0][ac0 + 6][arow] = pack2(ra1.z, ra1.z);
        AsD[0][ac0 + 7][arow] = pack2(ra1.w, ra1.w);
        *reinterpret_cast<float4*>(&Bs[0][brow][bc0])     = rb0;
        *reinterpret_cast<float4*>(&Bs[0][brow][bc0 + 4]) = rb1;
    }
    __syncthreads();

    const int ntiles = K >> 4;
    for (int kt = 0; kt < ntiles; kt++) {
        const int cur = kt & 1;
        const int nxt = cur ^ 1;

        if (kt + 1 < ntiles) {
            const float* Agn = Ag + (kt + 1) * 16;
            const float* Bgn = Bg + (size_t)(kt + 1) * 16 * ldb;
            ra0 = *reinterpret_cast<const float4*>(Agn);
            ra1 = *reinterpret_cast<const float4*>(Agn + 4);
            rb0 = *reinterpret_cast<const float4*>(Bgn);
            rb1 = *reinterpret_cast<const float4*>(Bgn + 4);
        }

        #pragma unroll
        for (int kk = 0; kk < 16; kk++) {
            const unsigned long long* ap = &AsD[cur][kk][ty * 8];
            ulonglong2 A01 = *reinterpret_cast<const ulonglong2*>(ap);
            ulonglong2 A23 = *reinterpret_cast<const ulonglong2*>(ap + 2);
            ulonglong2 A45 = *reinterpret_cast<const ulonglong2*>(ap + 4);
            ulonglong2 A67 = *reinterpret_cast<const ulonglong2*>(ap + 6);
            const float* bp = &Bs[cur][kk][tx * 8];
            ulonglong2 B01 = *reinterpret_cast<const ulonglong2*>(bp);
            ulonglong2 B23 = *reinterpret_cast<const ulonglong2*>(bp + 4);

            unsigned long long Av[8] = {A01.x, A01.y, A23.x, A23.y,
                                        A45.x, A45.y, A67.x, A67.y};
            unsigned long long Bv[4] = {B01.x, B01.y, B23.x, B23.y};

            #pragma unroll
            for (int i = 0; i < 8; i++) {
                #pragma unroll
                for (int j = 0; j < 4; j++)
                    fma2(acc2[i][j], Av[i], Bv[j]);
            }
        }

        if (kt + 1 < ntiles) {
            AsD[nxt][ac0 + 0][arow] = pack2(ra0.x, ra0.x);
            AsD[nxt][ac0 + 1][arow] = pack2(ra0.y, ra0.y);
            AsD[nxt][ac0 + 2][arow] = pack2(ra0.z, ra0.z);
            AsD[nxt][ac0 + 3][arow] = pack2(ra0.w, ra0.w);
            AsD[nxt][ac0 + 4][arow] = pack2(ra1.x, ra1.x);
            AsD[nxt][ac0 + 5][arow] = pack2(ra1.y, ra1.y);
            AsD[nxt][ac0 + 6][arow] = pack2(ra1.z, ra1.z);
            AsD[nxt][ac0 + 7][arow] = pack2(ra1.w, ra1.w);
            *reinterpret_cast<float4*>(&Bs[nxt][brow][bc0])     = rb0;
            *reinterpret_cast<float4*>(&Bs[nxt][brow][bc0 + 4]) = rb1;
        }
        __syncthreads();
    }

    // ---- epilogue ----
    #pragma unroll
    for (int i = 0; i < 8; i++) {
        int row = bm + ty * 8 + i;
        float* crow = C + (size_t)row * N;
        const float* x1row = X1 ? (X1 + (size_t)row * N) : nullptr;
        const float* x2row = X2 ? (X2 + (size_t)row * N) : nullptr;
        #pragma unroll
        for (int j = 0; j < 4; j++) {
            float lo, hi;
            unpack2(acc2[i][j], lo, hi);
            int col = bn + tx * 8 + 2 * j;
            #pragma unroll
            for (int h = 0; h < 2; h++) {
                float a = (h == 0) ? lo : hi;
                int c = col + h;
                if (!CGUARD || c < N) {
                    if (EPI == 0) {
                        crow[c] = a;
                    } else if (EPI == 1) {
                        crow[c] = a + x1row[c];
                    } else if (EPI == 2) {
                        float tpos = fmaxf(a, 0.f);
                        crow[c] = tpos * tpos;
                    } else if (EPI == 3) {
                        crow[c] = 1.f / (1.f + expf(-a));
                    } else {
                        crow[c] = x1row[c] + x2row[c] * a;
                    }
                }
            }
        }
    }
}

// ---------------- host orchestration ----------------
extern "C" void kernel_launch(void* const* d_in, const int* in_sizes, int n_in,
                              void* d_out, int out_size)
{
    const int*   tokens   = (const int*)  d_in[0];
    const float* emb      = (const float*)d_in[1];
    const float* tm_decay = (const float*)d_in[2];
    const float* tm_first = (const float*)d_in[3];
    const float* tm_mix_k = (const float*)d_in[4];
    const float* tm_mix_v = (const float*)d_in[5];
    const float* tm_mix_r = (const float*)d_in[6];
    const float* tm_Wk    = (const float*)d_in[7];
    const float* tm_Wv    = (const float*)d_in[8];
    const float* tm_Wr    = (const float*)d_in[9];
    const float* tm_Wo    = (const float*)d_in[10];
    const float* cm_mix_k = (const float*)d_in[11];
    const float* cm_mix_r = (const float*)d_in[12];
    const float* cm_Wk    = (const float*)d_in[13];
    const float* cm_Wv    = (const float*)d_in[14];
    const float* cm_Wr    = (const float*)d_in[15];
    const float* ln0_w    = (const float*)d_in[16];
    const float* ln0_b    = (const float*)d_in[17];
    const float* ln1_w    = (const float*)d_in[18];
    const float* ln1_b    = (const float*)d_in[19];
    const float* ln2_w    = (const float*)d_in[20];
    const float* ln2_b    = (const float*)d_in[21];
    const float* lnout_w  = (const float*)d_in[22];
    const float* lnout_b  = (const float*)d_in[23];
    const float* head_W   = (const float*)d_in[24];
    float* out = (float*)d_out;

    float *x_, *xn_, *xk_, *xv_, *xr_, *k_, *v_, *r_, *ry_, *rr_, *kk_, *hW_;
    cudaGetSymbolAddress((void**)&x_,  g_x);
    cudaGetSymbolAddress((void**)&xn_, g_xn);
    cudaGetSymbolAddress((void**)&xk_, g_xk);
    cudaGetSymbolAddress((void**)&xv_, g_xv);
    cudaGetSymbolAddress((void**)&xr_, g_xr);
    cudaGetSymbolAddress((void**)&k_,  g_k);
    cudaGetSymbolAddress((void**)&v_,  g_v);
    cudaGetSymbolAddress((void**)&r_,  g_r);
    cudaGetSymbolAddress((void**)&ry_, g_ry);
    cudaGetSymbolAddress((void**)&rr_, g_rr);
    cudaGetSymbolAddress((void**)&kk_, g_kk);
    cudaGetSymbolAddress((void**)&hW_, g_headW);

    const int ew = (Tn * Dn + 255) / 256;
    dim3 gDD(Dn / 128, Tn / 128);
    dim3 gDH(Hn / 128, Tn / 128);
    dim3 gHV(VP / 128, Tn / 128);

    // pad-copy head weight (gives aligned vector loads for head GEMM)
    padcopy_kernel<<<dim3(64, Dn), 256>>>(head_W, hW_);

    // embedding gather + ln0
    ln_kernel<<<Tn, 256>>>(emb, tokens, ln0_w, ln0_b, x_);

    for (int l = 0; l < Ln; l++) {
        const float* Wk  = tm_Wk + (size_t)l * Dn * Dn;
        const float* Wv  = tm_Wv + (size_t)l * Dn * Dn;
        const float* Wr  = tm_Wr + (size_t)l * Dn * Dn;
        const float* Wo  = tm_Wo + (size_t)l * Dn * Dn;
        const float* CWk = cm_Wk + (size_t)l * Dn * Hn;
        const float* CWv = cm_Wv + (size_t)l * Hn * Dn;
        const float* CWr = cm_Wr + (size_t)l * Dn * Dn;

        // ln1 (in-place; ln output becomes the residual stream)
        ln_kernel<<<Tn, 256>>>(x_, nullptr, ln1_w + l * Dn, ln1_b + l * Dn, x_);

        mix3_kernel<<<ew, 256>>>(x_, tm_mix_k + l * Dn, tm_mix_v + l * Dn,
                                 tm_mix_r + l * Dn, xk_, xv_, xr_);

        sgemm2_kernel<0, false><<<gDD, 256>>>(xk_, Wk, k_, Tn, Dn, Dn, Dn, nullptr, nullptr);
        sgemm2_kernel<0, false><<<gDD, 256>>>(xv_, Wv, v_, Tn, Dn, Dn, Dn, nullptr, nullptr);
        sgemm2_kernel<3, false><<<gDD, 256>>>(xr_, Wr, r_, Tn, Dn, Dn, Dn, nullptr, nullptr);

        wkv_kernel<<<Dn / 256, 256>>>(tm_decay + l * Dn, tm_first + l * Dn,
                                      k_, v_, r_, ry_);

        // x = x + (r*y) @ Wo
        sgemm2_kernel<1, false><<<gDD, 256>>>(ry_, Wo, x_, Tn, Dn, Dn, Dn, x_, nullptr);

        // channel mix
        ln_kernel<<<Tn, 256>>>(x_, nullptr, ln2_w + l * Dn, ln2_b + l * Dn, xn_);
        mix2_kernel<<<ew, 256>>>(xn_, cm_mix_k + l * Dn, cm_mix_r + l * Dn, xk_, xr_);

        sgemm2_kernel<2, false><<<gDH, 256>>>(xk_, CWk, kk_, Tn, Hn, Dn, Hn, nullptr, nullptr);
        sgemm2_kernel<3, false><<<gDD, 256>>>(xr_, CWr, rr_, Tn, Dn, Dn, Dn, nullptr, nullptr);
        // x = x + rr * (kk @ CWv)
        sgemm2_kernel<4, false><<<gDD, 256>>>(kk_, CWv, x_, Tn, Dn, Hn, Dn, x_, rr_);
    }

    // final LN + head (padded B, guarded C stores)
    ln_kernel<<<Tn, 256>>>(x_, nullptr, lnout_w, lnout_b, xn_);
    sgemm2_kernel<0, true><<<gHV, 256>>>(xn_, hW_, out, Tn, Vn, Dn, VP, nullptr, nullptr);
}

// round 5
// speedup vs baseline: 2.5050x; 2.1184x over previous
#include <cuda_runtime.h>
#include <cuda_bf16.h>
#include <math.h>
#include <stdint.h>

#define Tn 2048
#define Dn 1024
#define Hn 4096
#define Ln 8
#define Vn 50257
#define VP 50304
#define EPSn 1e-5f

// ---------------- scratch (no allocations allowed) ----------------
__device__ float g_x [Tn*Dn];
__device__ float g_xn[Tn*Dn];
__device__ float g_xk[Tn*Dn];
__device__ float g_xv[Tn*Dn];
__device__ float g_xr[Tn*Dn];
__device__ float g_k [Tn*Dn];
__device__ float g_v [Tn*Dn];
__device__ float g_r [Tn*Dn];
__device__ float g_ry[Tn*Dn];
__device__ float g_rr[Tn*Dn];
__device__ float g_kk[Tn*Hn];
__device__ float g_headW[(size_t)Dn * VP];

// ---------------- PTX helpers (all portable PTX, no sm_103a-only ops) -------
__device__ __forceinline__ uint32_t smem_u32(const void* p) {
    uint32_t a;
    asm("{ .reg .u64 t; cvta.to.shared.u64 t, %1; cvt.u32.u64 %0, t; }" : "=r"(a) : "l"(p));
    return a;
}

#define LDSM_X4(addr, r0, r1, r2, r3) \
    asm volatile("ldmatrix.sync.aligned.m8n8.x4.shared.b16 {%0,%1,%2,%3}, [%4];" \
        : "=r"(r0), "=r"(r1), "=r"(r2), "=r"(r3) : "r"(addr))

#define LDSM_X4T(addr, r0, r1, r2, r3) \
    asm volatile("ldmatrix.sync.aligned.m8n8.x4.trans.shared.b16 {%0,%1,%2,%3}, [%4];" \
        : "=r"(r0), "=r"(r1), "=r"(r2), "=r"(r3) : "r"(addr))

__device__ __forceinline__ void mma_bf16(float* c, const uint32_t* a,
                                         uint32_t b0, uint32_t b1) {
    asm volatile(
        "mma.sync.aligned.m16n8k16.row.col.f32.bf16.bf16.f32 "
        "{%0,%1,%2,%3}, {%4,%5,%6,%7}, {%8,%9}, {%0,%1,%2,%3};"
        : "+f"(c[0]), "+f"(c[1]), "+f"(c[2]), "+f"(c[3])
        : "r"(a[0]), "r"(a[1]), "r"(a[2]), "r"(a[3]), "r"(b0), "r"(b1));
}

__device__ __forceinline__ void sts4(uint32_t addr, uint32_t a, uint32_t b,
                                     uint32_t c, uint32_t d) {
    asm volatile("st.shared.v4.b32 [%0], {%1,%2,%3,%4};"
                 :: "r"(addr), "r"(a), "r"(b), "r"(c), "r"(d) : "memory");
}

// split x into bf16 hi/lo pair packed as {lo-half=elem0, hi-half=elem1}
__device__ __forceinline__ void split2(float x, float y, uint32_t& h, uint32_t& l) {
    __nv_bfloat16 hx = __float2bfloat16_rn(x);
    __nv_bfloat16 hy = __float2bfloat16_rn(y);
    float rx = x - __bfloat162float(hx);
    float ry = y - __bfloat162float(hy);
    __nv_bfloat162 hp; hp.x = hx; hp.y = hy;
    __nv_bfloat162 lp; lp.x = __float2bfloat16_rn(rx); lp.y = __float2bfloat16_rn(ry);
    h = *reinterpret_cast<uint32_t*>(&hp);
    l = *reinterpret_cast<uint32_t*>(&lp);
}

// ---------------- LayerNorm (optionally with embedding gather) ----------------
__global__ void __launch_bounds__(256)
ln_kernel(const float* __restrict__ x, const int* __restrict__ tokens,
          const float* __restrict__ w, const float* __restrict__ b,
          float* __restrict__ y)
{
    __shared__ float sh0[8], sh1[8];
    int t = blockIdx.x;
    const float* row;
    if (tokens) row = x + (size_t)tokens[t] * Dn;
    else        row = x + (size_t)t * Dn;

    float4 vv = reinterpret_cast<const float4*>(row)[threadIdx.x];
    float s  = vv.x + vv.y + vv.z + vv.w;
    float s2 = vv.x*vv.x + vv.y*vv.y + vv.z*vv.z + vv.w*vv.w;
    #pragma unroll
    for (int o = 16; o > 0; o >>= 1) {
        s  += __shfl_down_sync(0xffffffffu, s,  o);
        s2 += __shfl_down_sync(0xffffffffu, s2, o);
    }
    int wid = threadIdx.x >> 5, lid = threadIdx.x & 31;
    if (lid == 0) { sh0[wid] = s; sh1[wid] = s2; }
    __syncthreads();
    if (threadIdx.x < 32) {
        s  = (lid < 8) ? sh0[lid] : 0.f;
        s2 = (lid < 8) ? sh1[lid] : 0.f;
        #pragma unroll
        for (int o = 4; o > 0; o >>= 1) {
            s  += __shfl_down_sync(0xffffffffu, s,  o);
            s2 += __shfl_down_sync(0xffffffffu, s2, o);
        }
        if (lid == 0) { sh0[0] = s; sh1[0] = s2; }
    }
    __syncthreads();
    float mu  = sh0[0] * (1.f / Dn);
    float var = sh1[0] * (1.f / Dn) - mu * mu;
    float rstd = rsqrtf(var + EPSn);

    float4 wv = reinterpret_cast<const float4*>(w)[threadIdx.x];
    float4 bv = reinterpret_cast<const float4*>(b)[threadIdx.x];
    float4 o4;
    o4.x = (vv.x - mu) * rstd * wv.x + bv.x;
    o4.y = (vv.y - mu) * rstd * wv.y + bv.y;
    o4.z = (vv.z - mu) * rstd * wv.z + bv.z;
    o4.w = (vv.w - mu) * rstd * wv.w + bv.w;
    reinterpret_cast<float4*>(y + (size_t)t * Dn)[threadIdx.x] = o4;
}

// ---------------- time-shift mixes ----------------
__global__ void __launch_bounds__(256)
mix3_kernel(const float* __restrict__ x,
            const float* __restrict__ mk, const float* __restrict__ mv,
            const float* __restrict__ mr,
            float* __restrict__ xk, float* __restrict__ xv, float* __restrict__ xr)
{
    int i = blockIdx.x * 256 + threadIdx.x;
    if (i >= Tn * Dn) return;
    int d = i & (Dn - 1);
    float c = x[i];
    float p = (i >= Dn) ? x[i - Dn] : 0.f;
    float a;
    a = mk[d]; xk[i] = c * a + p * (1.f - a);
    a = mv[d]; xv[i] = c * a + p * (1.f - a);
    a = mr[d]; xr[i] = c * a + p * (1.f - a);
}

__global__ void __launch_bounds__(256)
mix2_kernel(const float* __restrict__ x,
            const float* __restrict__ mk, const float* __restrict__ mr,
            float* __restrict__ xk, float* __restrict__ xr)
{
    int i = blockIdx.x * 256 + threadIdx.x;
    if (i >= Tn * Dn) return;
    int d = i & (Dn - 1);
    float c = x[i];
    float p = (i >= Dn) ? x[i - Dn] : 0.f;
    float a;
    a = mk[d]; xk[i] = c * a + p * (1.f - a);
    a = mr[d]; xr[i] = c * a + p * (1.f - a);
}

// ---------------- WKV scan ----------------
__global__ void __launch_bounds__(256)
wkv_kernel(const float* __restrict__ td, const float* __restrict__ tf,
           const float* __restrict__ k, const float* __restrict__ v,
           const float* __restrict__ r, float* __restrict__ ry)
{
    int d = blockIdx.x * 256 + threadIdx.x;
    if (d >= Dn) return;
    float w = -expf(td[d]);
    float u = tf[d];
    float aa = 0.f, bb = 0.f, pp = -1e30f;
    float kt = k[d], vt = v[d];
    for (int t = 0; t < Tn; t++) {
        float kn = 0.f, vn = 0.f;
        if (t + 1 < Tn) { kn = k[(t + 1) * Dn + d]; vn = v[(t + 1) * Dn + d]; }
        float ww = u + kt;
        float qq = fmaxf(pp, ww);
        float e1 = __expf(pp - qq), e2 = __expf(ww - qq);
        float out = fmaf(e1, aa, e2 * vt) / fmaf(e1, bb, e2);
        float ww2 = pp + w;
        float qq2 = fmaxf(ww2, kt);
        e1 = __expf(ww2 - qq2); e2 = __expf(kt - qq2);
        aa = fmaf(e1, aa, e2 * vt);
        bb = fmaf(e1, bb, e2);
        pp = qq2;
        ry[t * Dn + d] = r[t * Dn + d] * out;
        kt = kn; vt = vn;
    }
}

// ---------------- head weight pad-copy ----------------
__global__ void __launch_bounds__(256)
padcopy_kernel(const float* __restrict__ src, float* __restrict__ dst)
{
    int r = blockIdx.y;
    for (int c = blockIdx.x * 256 + threadIdx.x; c < VP; c += gridDim.x * 256) {
        float v = (c < Vn) ? src[(size_t)r * Vn + c] : 0.f;
        dst[(size_t)r * VP + c] = v;
    }
}

// ---------------- bf16x2-split mma.sync GEMM, fused epilogues ----------------
// C[M,N] = epi(A[M,K] @ B[K,N]); B row stride ldb; M mult 128, K mult 32,
// grid covers N in 128-col tiles (B readable across the full tile width).
// EPI: 0 store, 1 acc+X1, 2 relu(acc)^2, 3 sigmoid(acc), 4 X1 + X2*acc

// smem stage layout (bytes): A rows padded to 80B (40 bf16), B rows to 272B
#define SA_H 0u
#define SA_L 10240u
#define SB_H 20480u
#define SB_L 29184u
#define STAGE_B 38144u
#define GEMM_SMEM (2 * 38144)

static __device__ __forceinline__ void stash_tiles(
    uint32_t st, const float4* ra, const float4* rb, uint32_t aw, uint32_t bw)
{
    uint32_t HA[8], LA[8], HB[8], LB[8];
    #pragma unroll
    for (int j = 0; j < 4; j++) {
        split2(ra[j].x, ra[j].y, HA[2*j],   LA[2*j]);
        split2(ra[j].z, ra[j].w, HA[2*j+1], LA[2*j+1]);
        split2(rb[j].x, rb[j].y, HB[2*j],   LB[2*j]);
        split2(rb[j].z, rb[j].w, HB[2*j+1], LB[2*j+1]);
    }
    sts4(st + SA_H + aw,      HA[0], HA[1], HA[2], HA[3]);
    sts4(st + SA_H + aw + 16, HA[4], HA[5], HA[6], HA[7]);
    sts4(st + SA_L + aw,      LA[0], LA[1], LA[2], LA[3]);
    sts4(st + SA_L + aw + 16, LA[4], LA[5], LA[6], LA[7]);
    sts4(st + SB_H + bw,      HB[0], HB[1], HB[2], HB[3]);
    sts4(st + SB_H + bw + 16, HB[4], HB[5], HB[6], HB[7]);
    sts4(st + SB_L + bw,      LB[0], LB[1], LB[2], LB[3]);
    sts4(st + SB_L + bw + 16, LB[4], LB[5], LB[6], LB[7]);
}

template<int EPI, bool CGUARD>
__global__ void __launch_bounds__(256, 1)
mgemm_kernel(const float* __restrict__ A, const float* __restrict__ B,
             float* __restrict__ C, int M, int N, int K, int ldb,
             const float* __restrict__ X1, const float* __restrict__ X2)
{
    extern __shared__ char dsm[];
    const int tid  = threadIdx.x;
    const int lane = tid & 31;
    const int wid  = tid >> 5;
    const int wm   = wid >> 2;      // 0..1  (64 rows each)
    const int wn   = wid & 3;       // 0..3  (32 cols each)
    const int bm   = blockIdx.y * 128;
    const int bn   = blockIdx.x * 128;

    const uint32_t sbase = smem_u32(dsm);

    // tile loaders
    const int ar = tid >> 1, ac = (tid & 1) * 16;   // A: 128 rows x 32 k
    const int br = tid >> 3, bc = (tid & 7) * 16;   // B: 32 k x 128 n
    const float* Ap = A + (size_t)(bm + ar) * K + ac;
    const float* Bp = B + (size_t)br * ldb + bn + bc;
    const uint32_t aw = (uint32_t)(ar * 80 + ac * 2);
    const uint32_t bw = (uint32_t)(br * 272 + bc * 2);

    // ldmatrix per-thread offsets
    const uint32_t a_off = (uint32_t)(((lane & 15) * 40 + ((lane >> 4) << 3)) * 2);
    const uint32_t b_off = (uint32_t)(((lane & 15) * 136 + ((lane >> 4) << 3)) * 2);

    float acc[4][4][4];
    #pragma unroll
    for (int i = 0; i < 4; i++)
        #pragma unroll
        for (int j = 0; j < 4; j++)
            #pragma unroll
            for (int q = 0; q < 4; q++) acc[i][j][q] = 0.f;

    float4 ra[4], rb[4];

    // preload chunk 0
    #pragma unroll
    for (int j = 0; j < 4; j++) {
        ra[j] = *reinterpret_cast<const float4*>(Ap + 4 * j);
        rb[j] = *reinterpret_cast<const float4*>(Bp + 4 * j);
    }
    stash_tiles(sbase, ra, rb, aw, bw);
    __syncthreads();

    const int nch = K >> 5;
    for (int kc = 0; kc < nch; kc++) {
        const uint32_t st = sbase + (uint32_t)(kc & 1) * STAGE_B;

        if (kc + 1 < nch) {
            const float* ap = Ap + (kc + 1) * 32;
            const float* bp = Bp + (size_t)((kc + 1) * 32) * ldb;
            #pragma unroll
            for (int j = 0; j < 4; j++) {
                ra[j] = *reinterpret_cast<const float4*>(ap + 4 * j);
                rb[j] = *reinterpret_cast<const float4*>(bp + 4 * j);
            }
        }

        #pragma unroll
        for (int ks = 0; ks < 2; ks++) {
            uint32_t bh[4][2], bl[4][2];
            #pragma unroll
            for (int p = 0; p < 2; p++) {
                uint32_t boff = (uint32_t)((ks * 16 * 136 + wn * 32 + p * 16) * 2) + b_off;
                LDSM_X4T(st + SB_H + boff, bh[2*p][0], bh[2*p][1], bh[2*p+1][0], bh[2*p+1][1]);
                LDSM_X4T(st + SB_L + boff, bl[2*p][0], bl[2*p][1], bl[2*p+1][0], bl[2*p+1][1]);
            }
            #pragma unroll
            for (int i = 0; i < 4; i++) {
                uint32_t ah[4], al[4];
                uint32_t aoff = (uint32_t)((((wm * 64 + i * 16) * 40) + ks * 16) * 2) + a_off;
                LDSM_X4(st + SA_H + aoff, ah[0], ah[1], ah[2], ah[3]);
                LDSM_X4(st + SA_L + aoff, al[0], al[1], al[2], al[3]);
                #pragma unroll
                for (int j = 0; j < 4; j++) {
                    mma_bf16(acc[i][j], ah, bh[j][0], bh[j][1]);
                    mma_bf16(acc[i][j], al, bh[j][0], bh[j][1]);
                    mma_bf16(acc[i][j], ah, bl[j][0], bl[j][1]);
                }
            }
        }

        if (kc + 1 < nch)
            stash_tiles(sbase + (uint32_t)((kc + 1) & 1) * STAGE_B, ra, rb, aw, bw);
        __syncthreads();
    }

    // ---- epilogue ----
    #pragma unroll
    for (int i = 0; i < 4; i++) {
        #pragma unroll
        for (int j = 0; j < 4; j++) {
            int row = bm + wm * 64 + i * 16 + (lane >> 2);
            int col = bn + wn * 32 + j * 8 + ((lane & 3) << 1);
            #pragma unroll
            for (int h = 0; h < 2; h++) {
                int rr = row + h * 8;
                float v0 = acc[i][j][2 * h + 0];
                float v1 = acc[i][j][2 * h + 1];
                float* crow = C + (size_t)rr * N;
                if (EPI == 1) {
                    const float* x1 = X1 + (size_t)rr * N;
                    v0 += x1[col]; v1 += x1[col + 1];
                } else if (EPI == 2) {
                    float p0 = fmaxf(v0, 0.f), p1 = fmaxf(v1, 0.f);
                    v0 = p0 * p0; v1 = p1 * p1;
                } else if (EPI == 3) {
                    v0 = 1.f / (1.f + expf(-v0));
                    v1 = 1.f / (1.f + expf(-v1));
                } else if (EPI == 4) {
                    const float* x1 = X1 + (size_t)rr * N;
                    const float* x2 = X2 + (size_t)rr * N;
                    v0 = x1[col]     + x2[col]     * v0;
                    v1 = x1[col + 1] + x2[col + 1] * v1;
                }
                if (CGUARD) {
                    if (col < N)     crow[col]     = v0;
                    if (col + 1 < N) crow[col + 1] = v1;
                } else {
                    float2 o = make_float2(v0, v1);
                    *reinterpret_cast<float2*>(crow + col) = o;
                }
            }
        }
    }
}

// ---------------- host orchestration ----------------
extern "C" void kernel_launch(void* const* d_in, const int* in_sizes, int n_in,
                              void* d_out, int out_size)
{
    const int*   tokens   = (const int*)  d_in[0];
    const float* emb      = (const float*)d_in[1];
    const float* tm_decay = (const float*)d_in[2];
    const float* tm_first = (const float*)d_in[3];
    const float* tm_mix_k = (const float*)d_in[4];
    const float* tm_mix_v = (const float*)d_in[5];
    const float* tm_mix_r = (const float*)d_in[6];
    const float* tm_Wk    = (const float*)d_in[7];
    const float* tm_Wv    = (const float*)d_in[8];
    const float* tm_Wr    = (const float*)d_in[9];
    const float* tm_Wo    = (const float*)d_in[10];
    const float* cm_mix_k = (const float*)d_in[11];
    const float* cm_mix_r = (const float*)d_in[12];
    const float* cm_Wk    = (const float*)d_in[13];
    const float* cm_Wv    = (const float*)d_in[14];
    const float* cm_Wr    = (const float*)d_in[15];
    const float* ln0_w    = (const float*)d_in[16];
    const float* ln0_b    = (const float*)d_in[17];
    const float* ln1_w    = (const float*)d_in[18];
    const float* ln1_b    = (const float*)d_in[19];
    const float* ln2_w    = (const float*)d_in[20];
    const float* ln2_b    = (const float*)d_in[21];
    const float* lnout_w  = (const float*)d_in[22];
    const float* lnout_b  = (const float*)d_in[23];
    const float* head_W   = (const float*)d_in[24];
    float* out = (float*)d_out;

    float *x_, *xn_, *xk_, *xv_, *xr_, *k_, *v_, *r_, *ry_, *rr_, *kk_, *hW_;
    cudaGetSymbolAddress((void**)&x_,  g_x);
    cudaGetSymbolAddress((void**)&xn_, g_xn);
    cudaGetSymbolAddress((void**)&xk_, g_xk);
    cudaGetSymbolAddress((void**)&xv_, g_xv);
    cudaGetSymbolAddress((void**)&xr_, g_xr);
    cudaGetSymbolAddress((void**)&k_,  g_k);
    cudaGetSymbolAddress((void**)&v_,  g_v);
    cudaGetSymbolAddress((void**)&r_,  g_r);
    cudaGetSymbolAddress((void**)&ry_, g_ry);
    cudaGetSymbolAddress((void**)&rr_, g_rr);
    cudaGetSymbolAddress((void**)&kk_, g_kk);
    cudaGetSymbolAddress((void**)&hW_, g_headW);

    cudaFuncSetAttribute(mgemm_kernel<0,false>, cudaFuncAttributeMaxDynamicSharedMemorySize, GEMM_SMEM);
    cudaFuncSetAttribute(mgemm_kernel<1,false>, cudaFuncAttributeMaxDynamicSharedMemorySize, GEMM_SMEM);
    cudaFuncSetAttribute(mgemm_kernel<2,false>, cudaFuncAttributeMaxDynamicSharedMemorySize, GEMM_SMEM);
    cudaFuncSetAttribute(mgemm_kernel<3,false>, cudaFuncAttributeMaxDynamicSharedMemorySize, GEMM_SMEM);
    cudaFuncSetAttribute(mgemm_kernel<4,false>, cudaFuncAttributeMaxDynamicSharedMemorySize, GEMM_SMEM);
    cudaFuncSetAttribute(mgemm_kernel<0,true>,  cudaFuncAttributeMaxDynamicSharedMemorySize, GEMM_SMEM);

    const int ew = (Tn * Dn + 255) / 256;
    dim3 gDD(Dn / 128, Tn / 128);
    dim3 gDH(Hn / 128, Tn / 128);
    dim3 gHV(VP / 128, Tn / 128);

    padcopy_kernel<<<dim3(64, Dn), 256>>>(head_W, hW_);

    ln_kernel<<<Tn, 256>>>(emb, tokens, ln0_w, ln0_b, x_);

    for (int l = 0; l < Ln; l++) {
        const float* Wk  = tm_Wk + (size_t)l * Dn * Dn;
        const float* Wv  = tm_Wv + (size_t)l * Dn * Dn;
        const float* Wr  = tm_Wr + (size_t)l * Dn * Dn;
        const float* Wo  = tm_Wo + (size_t)l * Dn * Dn;
        const float* CWk = cm_Wk + (size_t)l * Dn * Hn;
        const float* CWv = cm_Wv + (size_t)l * Hn * Dn;
        const float* CWr = cm_Wr + (size_t)l * Dn * Dn;

        ln_kernel<<<Tn, 256>>>(x_, nullptr, ln1_w + l * Dn, ln1_b + l * Dn, x_);

        mix3_kernel<<<ew, 256>>>(x_, tm_mix_k + l * Dn, tm_mix_v + l * Dn,
                                 tm_mix_r + l * Dn, xk_, xv_, xr_);

        mgemm_kernel<0,false><<<gDD, 256, GEMM_SMEM>>>(xk_, Wk, k_, Tn, Dn, Dn, Dn, nullptr, nullptr);
        mgemm_kernel<0,false><<<gDD, 256, GEMM_SMEM>>>(xv_, Wv, v_, Tn, Dn, Dn, Dn, nullptr, nullptr);
        mgemm_kernel<3,false><<<gDD, 256, GEMM_SMEM>>>(xr_, Wr, r_, Tn, Dn, Dn, Dn, nullptr, nullptr);

        wkv_kernel<<<Dn / 256, 256>>>(tm_decay + l * Dn, tm_first + l * Dn,
                                      k_, v_, r_, ry_);

        mgemm_kernel<1,false><<<gDD, 256, GEMM_SMEM>>>(ry_, Wo, x_, Tn, Dn, Dn, Dn, x_, nullptr);

        ln_kernel<<<Tn, 256>>>(x_, nullptr, ln2_w + l * Dn, ln2_b + l * Dn, xn_);
        mix2_kernel<<<ew, 256>>>(xn_, cm_mix_k + l * Dn, cm_mix_r + l * Dn, xk_, xr_);

        mgemm_kernel<2,false><<<gDH, 256, GEMM_SMEM>>>(xk_, CWk, kk_, Tn, Hn, Dn, Hn, nullptr, nullptr);
        mgemm_kernel<3,false><<<gDD, 256, GEMM_SMEM>>>(xr_, CWr, rr_, Tn, Dn, Dn, Dn, nullptr, nullptr);
        mgemm_kernel<4,false><<<gDD, 256, GEMM_SMEM>>>(kk_, CWv, x_, Tn, Dn, Hn, Dn, x_, rr_);
    }

    ln_kernel<<<Tn, 256>>>(x_, nullptr, lnout_w, lnout_b, xn_);
    mgemm_kernel<0,true><<<gHV, 256, GEMM_SMEM>>>(xn_, hW_, out, Tn, Vn, Dn, VP, nullptr, nullptr);
}